// round 17
// baseline (speedup 1.0000x reference)
#include <cuda_runtime.h>
#include <cuda_fp16.h>
#include <cstdint>
#include <math.h>

#define BATCH 4
#define SEQ   2048
#define HID   768
#define NQKV  (3*HID)
#define TOK   (BATCH*SEQ)   // 8192

// ---------------- scratch (device globals; allocation-free) ----------------
__device__ __align__(128) __half g_xh [(size_t)TOK*HID];
__device__ __align__(128) __half g_wh [(size_t)NQKV*HID];
__device__ __align__(128) __half g_qh [(size_t)TOK*HID];
__device__ __align__(128) __half g_kh [(size_t)TOK*HID];
__device__ __align__(128) __half g_vTh[(size_t)BATCH*HID*SEQ];
__device__ __align__(128) __half g_ph [(size_t)BATCH*SEQ*SEQ];   // unnormalized exp(scores), fp16
__device__ __align__(128) float  g_rsum[(size_t)BATCH*SEQ];      // row sums (atomic accum)

// ---------------- PTX helpers (sm_80-compatible only) ----------------
__device__ __forceinline__ uint32_t smem_u32(const void* p) {
    uint32_t a;
    asm("{ .reg .u64 t; cvta.to.shared.u64 t, %1; cvt.u32.u64 %0, t; }" : "=r"(a) : "l"(p));
    return a;
}
__device__ __forceinline__ void cp16(uint32_t dst, const void* src) {
    asm volatile("cp.async.cg.shared.global [%0], [%1], 16;" :: "r"(dst), "l"(src));
}
#define CP_COMMIT() asm volatile("cp.async.commit_group;" ::: "memory")
#define CP_WAIT1()  asm volatile("cp.async.wait_group 1;" ::: "memory")

__device__ __forceinline__ void ldm4(uint32_t* r, uint32_t addr) {
    asm volatile("ldmatrix.sync.aligned.m8n8.x4.shared.b16 {%0,%1,%2,%3}, [%4];"
                 : "=r"(r[0]), "=r"(r[1]), "=r"(r[2]), "=r"(r[3]) : "r"(addr));
}
__device__ __forceinline__ void mma16816(float* c, const uint32_t* a, const uint32_t* b) {
    asm volatile("mma.sync.aligned.m16n8k16.row.col.f32.f16.f16.f32 "
                 "{%0,%1,%2,%3}, {%4,%5,%6,%7}, {%8,%9}, {%0,%1,%2,%3};"
                 : "+f"(c[0]), "+f"(c[1]), "+f"(c[2]), "+f"(c[3])
                 : "r"(a[0]), "r"(a[1]), "r"(a[2]), "r"(a[3]), "r"(b[0]), "r"(b[1]));
}

// SW128-style swizzle for 128B rows: XOR off[9:7] into off[6:4].
__device__ __forceinline__ uint32_t swz(uint32_t off) {
    return off ^ ((off >> 3) & 0x70u);
}

// -------- persistent HMMA GEMM: C[128x128] tiles = A(MxK) · B(NxK)^T --------
// K-chunk = 64, swizzled 128B rows, 2 tiles/stage, 3 stages, 2 CTAs/SM.
// Grid = 2*SMs persistent CTAs; flat chunk stream keeps the cp.async pipeline
// rolling across tile boundaries (no per-tile refill, no tail wave).
#define ROWB    128
#define TILE_B  (128*ROWB)          // 16384
#define STAGE_B (2*TILE_B)          // 32768
#define NSTAGE  3
#define SM_TOTAL (NSTAGE*STAGE_B)   // 98304 (x2 CTAs = 196608)

// EPI: 0 = QKV (bias; Q,K fp16, V fp16 transposed)
//      1 = QK: P = exp(score) fp16 + per-row atomic partial sums into g_rsum
//      2 = PV: f32 out scaled by 1/g_rsum[row]
template<int EPI>
__global__ __launch_bounds__(256, 2)
void hmma_gemm(const __half* __restrict__ Ah, const __half* __restrict__ Bh,
               long long lda, long long ldb, int K,
               long long sA, long long sB,
               const float* __restrict__ bias, float alpha,
               void* __restrict__ Cp, long long ldc, long long sC,
               int NX, int NY, int T)
{
    extern __shared__ char smem[];
    const uint32_t sbase = smem_u32(smem);
    const int tid = threadIdx.x;
    const int bid = blockIdx.x, G = gridDim.x;
    const int wid = tid >> 5, lane = tid & 31;
    const int wm = wid & 1;          // 2 warps in M (64 rows each)
    const int wn = wid >> 1;         // 4 warps in N (32 cols each)

    if (bid >= T) return;
    const int myT = (T - 1 - bid) / G + 1;   // tiles: bid, bid+G, ...
    const int nch = K / 64;
    const int total = myT * nch;

    // per-thread ldmatrix lane addressing (pre-swizzle offsets)
    const int m_in = (lane & 7) + 8 * ((lane >> 3) & 1);
    const int kb_a = (lane >> 4) * 16;
    const int n_in = (lane & 7) + 8 * (lane >> 4);
    const int kb_b = ((lane >> 3) & 1) * 16;
    const uint32_t a_row_off = (uint32_t)((wm * 64 + m_in) * ROWB + kb_a);
    const uint32_t b_row_off = (uint32_t)((wn * 32 + n_in) * ROWB + kb_b);

    float acc[4][4][4];
    #pragma unroll
    for (int i = 0; i < 4; i++)
        #pragma unroll
        for (int j = 0; j < 4; j++)
            #pragma unroll
            for (int r = 0; r < 4; r++) acc[i][j][r] = 0.f;

    // load one 64-K chunk of tile (bid + ti*G), chunk c, into stage slot
    auto load_chunk = [&](int ti, int c, int slot) {
        int t = bid + ti * G;
        int tbx = t % NX; int r0 = t / NX; int tby = r0 % NY; int tbz = r0 / NY;
        const __half* a_h = Ah + tbz * sA + (long long)tby * 128 * lda;
        const __half* b_h = Bh + tbz * sB + (long long)tbx * 128 * ldb;
        const uint32_t dbase = sbase + (uint32_t)slot * STAGE_B;
        const long long k0 = (long long)c * 64;
        #pragma unroll
        for (int tt = 0; tt < 2; tt++) {
            const __half* src = (tt == 0) ? a_h : b_h;
            const long long ld = (tt == 0) ? lda : ldb;
            #pragma unroll
            for (int p = 0; p < 4; p++) {
                int idx = tid + p * 256;        // 0..1023
                int r = idx >> 3, ch = idx & 7;
                cp16(dbase + (uint32_t)tt * TILE_B + swz((uint32_t)(r * ROWB + ch * 16)),
                     src + (long long)r * ld + k0 + ch * 8);
            }
        }
    };

    load_chunk(0, 0, 0); CP_COMMIT();
    load_chunk(0, 1, 1); CP_COMMIT();
    int li = 0, lc = 2;                 // next (tile, chunk) to load
    if (lc >= nch) { lc -= nch; li++; } // (nch >= 12 always, but keep safe)
    int ci = 0, cc = 0;                 // current compute (tile, chunk)

    for (int g = 0; g < total; g++) {
        CP_WAIT1();
        __syncthreads();
        if (g + 2 < total) {
            load_chunk(li, lc, (g + 2) % NSTAGE);
            if (++lc == nch) { lc = 0; li++; }
        }
        CP_COMMIT();

        const uint32_t st = sbase + (uint32_t)(g % NSTAGE) * STAGE_B;
        #pragma unroll
        for (int ks = 0; ks < 4; ks++) {
            uint32_t ah[4][4], bh[2][4];
            #pragma unroll
            for (int mi = 0; mi < 4; mi++) {
                uint32_t ao = a_row_off + (uint32_t)(mi * 16 * ROWB + ks * 32);
                ldm4(ah[mi], st + swz(ao));
            }
            #pragma unroll
            for (int nj = 0; nj < 2; nj++) {
                uint32_t bo = b_row_off + (uint32_t)(nj * 16 * ROWB + ks * 32);
                ldm4(bh[nj], st + TILE_B + swz(bo));
            }
            #pragma unroll
            for (int mi = 0; mi < 4; mi++)
                #pragma unroll
                for (int ni = 0; ni < 4; ni++)
                    mma16816(acc[mi][ni], ah[mi], &bh[ni >> 1][(ni & 1) * 2]);
        }

        if (++cc == nch) {
            // ---------------- epilogue for tile ci ----------------
            int t = bid + ci * G;
            int bx = t % NX; int r0 = t / NX; int by = r0 % NY; int bz = r0 / NY;
            const int gl = lane >> 2, t4 = lane & 3;
            const int row0 = by * 128 + wm * 64 + gl;
            const int col0 = bx * 128 + wn * 32 + t4 * 2;

            if (EPI == 0) {
                const int seg = (bx * 128) / HID;   // 0=Q, 1=K, 2=V
                #pragma unroll
                for (int mi = 0; mi < 4; mi++)
                    #pragma unroll
                    for (int ni = 0; ni < 4; ni++)
                        #pragma unroll
                        for (int h = 0; h < 2; h++) {
                            long long row = row0 + mi * 16 + h * 8;
                            int col = col0 + ni * 8;
                            float v0 = acc[mi][ni][h * 2 + 0] + bias[col];
                            float v1 = acc[mi][ni][h * 2 + 1] + bias[col + 1];
                            __half h0 = __float2half_rn(v0);
                            __half h1 = __float2half_rn(v1);
                            if (seg == 0) {
                                *reinterpret_cast<__half2*>(g_qh + row * HID + col) = __half2(h0, h1);
                            } else if (seg == 1) {
                                *reinterpret_cast<__half2*>(g_kh + row * HID + (col - HID)) = __half2(h0, h1);
                            } else {
                                int hh = col - 2 * HID;
                                int b = (int)(row >> 11), s = (int)(row & 2047);
                                size_t o0 = ((size_t)b * HID + hh) * SEQ + s;
                                g_vTh[o0] = h0;
                                g_vTh[o0 + SEQ] = h1;
                            }
                        }
            } else if (EPI == 1) {
                __half* cb = (__half*)Cp + bz * sC;
                float* rsp = g_rsum + (size_t)bz * SEQ;
                #pragma unroll
                for (int mi = 0; mi < 4; mi++)
                    #pragma unroll
                    for (int h = 0; h < 2; h++) {
                        long long row = row0 + mi * 16 + h * 8;
                        float part = 0.f;
                        #pragma unroll
                        for (int ni = 0; ni < 4; ni++) {
                            int col = col0 + ni * 8;
                            float p0 = exp2f(alpha * acc[mi][ni][h * 2 + 0]);
                            float p1 = exp2f(alpha * acc[mi][ni][h * 2 + 1]);
                            part += p0 + p1;
                            *reinterpret_cast<__half2*>(cb + row * ldc + col) =
                                __half2(__float2half_rn(p0), __float2half_rn(p1));
                        }
                        part += __shfl_xor_sync(0xffffffffu, part, 1);
                        part += __shfl_xor_sync(0xffffffffu, part, 2);
                        if (t4 == 0) atomicAdd(rsp + row, part);
                    }
            } else {
                float* cb = (float*)Cp + bz * sC;
                const float* rsb = g_rsum + (size_t)bz * SEQ;
                #pragma unroll
                for (int mi = 0; mi < 4; mi++)
                    #pragma unroll
                    for (int h = 0; h < 2; h++) {
                        long long row = row0 + mi * 16 + h * 8;
                        float s = 1.f / rsb[row];
                        #pragma unroll
                        for (int ni = 0; ni < 4; ni++) {
                            int col = col0 + ni * 8;
                            float2 o;
                            o.x = s * acc[mi][ni][h * 2 + 0];
                            o.y = s * acc[mi][ni][h * 2 + 1];
                            *reinterpret_cast<float2*>(cb + row * ldc + col) = o;
                        }
                    }
            }
            // reset accumulators for next tile
            #pragma unroll
            for (int i = 0; i < 4; i++)
                #pragma unroll
                for (int j = 0; j < 4; j++)
                    #pragma unroll
                    for (int r = 0; r < 4; r++) acc[i][j][r] = 0.f;
            cc = 0; ci++;
        }
    }
}

// ------- fp32 -> fp16 convert (X and W) + zero rsum, one launch -------------
__global__ __launch_bounds__(256)
void cvt_all(const float* __restrict__ X, const float* __restrict__ W,
             __half* __restrict__ xh, __half* __restrict__ wh,
             float* __restrict__ rs, int nX4, int nW4)
{
    int i = blockIdx.x * 256 + threadIdx.x;
    if (i < TOK / 4)
        reinterpret_cast<float4*>(rs)[i] = make_float4(0.f, 0.f, 0.f, 0.f);
    const float* src;
    __half* dst;
    int j;
    if (i < nX4)            { src = X; dst = xh; j = i; }
    else if (i < nX4 + nW4) { src = W; dst = wh; j = i - nX4; }
    else return;
    float4 v = reinterpret_cast<const float4*>(src)[j];
    reinterpret_cast<__half2*>(dst)[2*j]   = __half2(__float2half_rn(v.x), __float2half_rn(v.y));
    reinterpret_cast<__half2*>(dst)[2*j+1] = __half2(__float2half_rn(v.z), __float2half_rn(v.w));
}

// ---------------------------------------------------------------------------
extern "C" void kernel_launch(void* const* d_in, const int* in_sizes, int n_in,
                              void* d_out, int out_size)
{
    const float* X = (const float*)d_in[0];
    const float* W = (const float*)d_in[1];
    const float* b = (const float*)d_in[2];
    float* out = (float*)d_out;

    static int G = 0;
    if (G == 0) {
        int dev = 0, sms = 148;
        cudaGetDevice(&dev);
        cudaDeviceGetAttribute(&sms, cudaDevAttrMultiProcessorCount, dev);
        G = 2 * sms;
        cudaFuncSetAttribute(hmma_gemm<0>, cudaFuncAttributeMaxDynamicSharedMemorySize, SM_TOTAL);
        cudaFuncSetAttribute(hmma_gemm<1>, cudaFuncAttributeMaxDynamicSharedMemorySize, SM_TOTAL);
        cudaFuncSetAttribute(hmma_gemm<2>, cudaFuncAttributeMaxDynamicSharedMemorySize, SM_TOTAL);
    }

    void *xh, *wh, *qh, *kh, *vTh, *ph, *rs;
    cudaGetSymbolAddress(&xh, g_xh);
    cudaGetSymbolAddress(&wh, g_wh);
    cudaGetSymbolAddress(&qh, g_qh);
    cudaGetSymbolAddress(&kh, g_kh);
    cudaGetSymbolAddress(&vTh, g_vTh);
    cudaGetSymbolAddress(&ph, g_ph);
    cudaGetSymbolAddress(&rs, g_rsum);

    const int nX4 = TOK * HID / 4;      // 1,572,864
    const int nW4 = NQKV * HID / 4;     //   442,368

    // 1) zero rsum + convert inputs to fp16 (single launch)
    cvt_all<<<(nX4 + nW4 + 255) / 256, 256>>>(X, W, (__half*)xh, (__half*)wh,
                                              (float*)rs, nX4, nW4);

    // 2) QKV = X @ W^T + b  (tiles: 18 x 64 x 1)
    hmma_gemm<0><<<G, 256, SM_TOTAL>>>(
        (__half*)xh, (__half*)wh,
        HID, HID, HID, 0LL, 0LL, b, 1.0f, nullptr, 0LL, 0LL,
        NQKV / 128, TOK / 128, (NQKV / 128) * (TOK / 128));

    // 3) P = exp(Q @ K^T / sqrt(768)) fp16 + row sums (tiles: 16 x 16 x 4)
    const float alpha = 1.44269504f * rsqrtf((float)HID);   // log2(e)/sqrt(HID)
    hmma_gemm<1><<<G, 256, SM_TOTAL>>>(
        (__half*)qh, (__half*)kh,
        HID, HID, HID, (long long)SEQ * HID, (long long)SEQ * HID,
        nullptr, alpha, ph, SEQ, (long long)SEQ * SEQ,
        SEQ / 128, SEQ / 128, (SEQ / 128) * (SEQ / 128) * BATCH);

    // 4) out = (P @ V) / rowsum  (tiles: 6 x 16 x 4)
    hmma_gemm<2><<<G, 256, SM_TOTAL>>>(
        (__half*)ph, (__half*)vTh,
        SEQ, SEQ, SEQ, (long long)SEQ * SEQ, (long long)HID * SEQ,
        nullptr, 1.0f, out, HID, (long long)SEQ * HID,
        HID / 128, SEQ / 128, (HID / 128) * (SEQ / 128) * BATCH);
}